// round 6
// baseline (speedup 1.0000x reference)
#include <cuda_runtime.h>
#include <cuda_bf16.h>
#include <cstdint>

// ---------------------------------------------------------------------------
// Quantized "LUT" conv == plain int8 conv (lut[a+128][b+128] == a*b exactly):
//   T_f = 2.85 + 0.05*max|x| ; T_w = 0.285 + 0.05*max|w|
//   s_x = T_f/127 ; s_w = T_w/127
//   out = int8conv(clip(rint(x/s_x)), clip(rint(w/s_w))) * (s_x*s_w) + bias
// Integer accumulation is bit-identical to the f32 reference.
//
// R6: single kernel with PROVABLE co-residency: GRID=444=148*3, THR=224,
// __launch_bounds__(224,3) (<=97 regs), smem 24.8KB*3=74.5KB/SM. Ticket
// barriers in R3's (verified-correct) form. Scales computed per-block after
// barrier 1; absmax reset by block 0 after barrier 2. Conv = 448 co-half
// tiles, coh = t&1 so a block's tiles share one staged weight half.
// ---------------------------------------------------------------------------

#define B_   8
#define C_   64
#define H_   28
#define W_   28
#define WP   30
#define NX   (B_ * C_ * H_ * W_)   // 401408
#define NW   (C_ * C_ * 9)         // 36864
#define GRID 444
#define THR  224
#define NTHR (GRID * THR)          // 99456

#define WROW_W 148                 // smem words per co row (144 + 4 pad)
#define XROW_W (WP * 16)           // 480 words per padded x row

// device scratch (allocation-free). g_bar1/g_bar2 monotonic (never reset,
// each launch adds exactly GRID) -> replay-safe. g_absmax reset in-kernel.
__device__ unsigned long long g_bar1, g_bar2;
__device__ unsigned int       g_absmax[2];
__device__ signed char        g_qw[C_ * 9 * C_];    // [co][kh][kw][ci]

__device__ __forceinline__ int quant1(float v, float s) {
    float q = rintf(__fdiv_rn(v, s));
    q = fminf(fmaxf(q, -128.0f), 127.0f);
    return (int)q;
}
__device__ __forceinline__ float amax4(float4 v) {
    return fmaxf(fmaxf(fabsf(v.x), fabsf(v.y)), fmaxf(fabsf(v.z), fabsf(v.w)));
}

__global__ __launch_bounds__(THR, 3) void fused_kernel(
    const float* __restrict__ x, const float* __restrict__ wgt,
    const float* __restrict__ bias, float* __restrict__ out)
{
    __shared__ int   s_qw[32 * WROW_W];   // 18944 B
    __shared__ int   s_x[3 * XROW_W];     // 5760 B
    __shared__ float s_red[14];
    __shared__ float s_sc[2];

    const int tid  = threadIdx.x;
    const int bid  = blockIdx.x;
    const int gtid = bid * THR + tid;     // [0, 99456)

    // ---------------- Phase A: absmax ------------------------------------
    const float4* x4 = (const float4*)x;
    float mx = amax4(x4[gtid]);                       // NX/4 = 100352
    if (gtid < NX / 4 - NTHR) mx = fmaxf(mx, amax4(x4[gtid + NTHR]));
    float mw = 0.0f;
    if (gtid < NW / 4) mw = amax4(((const float4*)wgt)[gtid]);

    #pragma unroll
    for (int o = 16; o; o >>= 1) {
        mx = fmaxf(mx, __shfl_xor_sync(0xffffffffu, mx, o));
        mw = fmaxf(mw, __shfl_xor_sync(0xffffffffu, mw, o));
    }
    if ((tid & 31) == 0) { s_red[tid >> 5] = mx; s_red[7 + (tid >> 5)] = mw; }
    __syncthreads();

    // leader: 2 atomics, ticket barrier 1, scales computed locally
    if (tid == 0) {
        float a = 0.0f, b = 0.0f;
        #pragma unroll
        for (int i = 0; i < 7; i++) {
            a = fmaxf(a, s_red[i]);
            b = fmaxf(b, s_red[7 + i]);
        }
        atomicMax(&g_absmax[0], __float_as_uint(a));   // vals >= 0: uint order
        atomicMax(&g_absmax[1], __float_as_uint(b));
        __threadfence();
        unsigned long long t = atomicAdd(&g_bar1, 1ull);
        unsigned long long tgt = t - (t % GRID) + GRID;
        while (atomicAdd(&g_bar1, 0ull) < tgt) __nanosleep(32);
        __threadfence();
        float amx = __uint_as_float(__ldcg(&g_absmax[0]));
        float amw = __uint_as_float(__ldcg(&g_absmax[1]));
        float Tf = __fadd_rn(2.85f,  __fmul_rn(0.05f, amx));
        float Tw = __fadd_rn(0.285f, __fmul_rn(0.05f, amw));
        float sx = __fdiv_rn(Tf, 127.0f);
        float sw = __fdiv_rn(Tw, 127.0f);
        s_sc[0] = sx;
        s_sc[1] = __fmul_rn(sx, sw);
        if (gtid < NW / 4) {}          // keep symmetric, no-op
        // weight-quant scale needed below by first 9216 threads:
        s_red[0] = sw;                 // reuse smem slot (post-read)
    }
    __syncthreads();

    const float sx   = s_sc[0];
    const float prod = s_sc[1];
    const float sw_q = s_red[0];

    // ---------------- Phase B: distributed weight quant -------------------
    if (gtid < NW / 4) {
        int cig = gtid & 15;              // group of 4 ci
        int r   = gtid >> 4;              // co*9 + kh*3 + kw
        int co  = r / 9;
        int khw = r - co * 9;
        const float* src = wgt + co * 576 + cig * 36 + khw;
        int q0 = quant1(src[0],  sw_q);
        int q1 = quant1(src[9],  sw_q);
        int q2 = quant1(src[18], sw_q);
        int q3 = quant1(src[27], sw_q);
        ((int*)g_qw)[gtid] = (q0 & 255) | ((q1 & 255) << 8) |
                             ((q2 & 255) << 16) | (q3 << 24);
    }

    // ticket barrier 2: all g_qw writes visible before staging
    if (tid == 0) {
        __threadfence();
        unsigned long long t = atomicAdd(&g_bar2, 1ull);
        unsigned long long tgt = t - (t % GRID) + GRID;
        while (atomicAdd(&g_bar2, 0ull) < tgt) __nanosleep(32);
        __threadfence();
        if (bid == 0) {                    // all absmax reads done (pre-bar2)
            g_absmax[0] = 0u;
            g_absmax[1] = 0u;
        }
    }
    __syncthreads();

    // ---------------- Phase C: conv, 448 co-half tiles --------------------
    const int coh = bid & 1;
    {   // stage this block's weight half once (tiles share coh)
        const int4* gw = (const int4*)(g_qw + coh * 32 * 576);
        for (int i = tid; i < 32 * 36; i += THR) {
            int co_l = i / 36;
            int j    = i - co_l * 36;
            ((int4*)(s_qw + co_l * WROW_W))[j] = __ldcg(gw + i);
        }
    }

    const int co_l = tid & 31;
    const int owg  = tid >> 5;            // 0..6
    const int co   = coh * 32 + co_l;
    const int* wbase = s_qw + co_l * WROW_W;
    const float bco  = bias[co];

    for (int t = bid; t < 448; t += GRID) {          // t&1 == coh always
        const int idx = t >> 1;                      // [0, 224)
        const int b   = idx / 28;
        const int oh  = idx - b * 28;

        for (int i = tid; i < 3 * XROW_W; i += THR) s_x[i] = 0;
        __syncthreads();

        // quantize 3 input rows (r = oh-1+kh) into s_x[kh][w+1][cg]
        for (int i = tid; i < 16 * 3 * W_; i += THR) {
            int w  = i % W_;
            int r2 = i / W_;              // cg*3 + kh
            int kh = r2 % 3;
            int cg = r2 / 3;
            int r  = oh - 1 + kh;
            if (r >= 0 && r < H_) {
                const float* src = x + (b * 64 + cg * 4) * 784 + r * W_ + w;
                int q0 = quant1(src[0],    sx);
                int q1 = quant1(src[784],  sx);
                int q2 = quant1(src[1568], sx);
                int q3 = quant1(src[2352], sx);
                s_x[(kh * WP + w + 1) * 16 + cg] =
                    (q0 & 255) | ((q1 & 255) << 8) |
                    ((q2 & 255) << 16) | (q3 << 24);
            }
        }
        __syncthreads();

        int acc[4];
        #pragma unroll
        for (int i = 0; i < 4; i++) acc[i] = 0;

        #pragma unroll
        for (int kh = 0; kh < 3; kh++) {
            const int* xrow = s_x + kh * XROW_W + owg * 4 * 16;
            const int* wrow = wbase + kh * 48;
            #pragma unroll
            for (int jj = 0; jj < 12; jj++) {
                int4 w4 = *(const int4*)(wrow + jj * 4);
                #pragma unroll
                for (int i = 0; i < 4; i++) {
                    int4 x4v = *(const int4*)(xrow + i * 16 + jj * 4);
                    int a = acc[i];
                    a = __dp4a(x4v.x, w4.x, a);
                    a = __dp4a(x4v.y, w4.y, a);
                    a = __dp4a(x4v.z, w4.z, a);
                    a = __dp4a(x4v.w, w4.w, a);
                    acc[i] = a;
                }
            }
        }

        float* obase = out + ((b * C_ + co) * H_ + oh) * W_ + owg * 4;
        #pragma unroll
        for (int i = 0; i < 4; i++)
            obase[i] = __fadd_rn(__fmul_rn((float)acc[i], prod), bco);
        __syncthreads();                 // protect s_x before next tile
    }
}

// ---------------------------------------------------------------------------
extern "C" void kernel_launch(void* const* d_in, const int* in_sizes, int n_in,
                              void* d_out, int out_size)
{
    const float* x    = (const float*)d_in[0];   // (8,64,28,28)
    const float* wgt  = (const float*)d_in[1];   // (64,64,3,3)
    const float* bias = (const float*)d_in[2];   // (64,)
    // d_in[3] = lut: lut[a+128,b+128] == a*b -> folded into integer MAC
    float* out = (float*)d_out;

    fused_kernel<<<GRID, THR>>>(x, wgt, bias, out);
    (void)in_sizes; (void)n_in; (void)out_size;
}

// round 7
// speedup vs baseline: 1.4181x; 1.4181x over previous
#include <cuda_runtime.h>
#include <cuda_bf16.h>
#include <cstdint>

// ---------------------------------------------------------------------------
// Quantized "LUT" conv == plain int8 conv (lut[a+128][b+128] == a*b exactly):
//   T_f = 2.85 + 0.05*max|x| ; T_w = 0.285 + 0.05*max|w|
//   s_x = T_f/127 ; s_w = T_w/127
//   out = int8conv(clip(rint(x/s_x)), clip(rint(w/s_w))) * (s_x*s_w) + bias
// Integer accumulation is bit-identical to the f32 reference.
//
// R7: R4's 3-node pipeline + PDL (programmatic dependent launch). Consumers
// launch early (programmatic stream serialization), prefetch producer-
// independent inputs into registers, then griddepcontrol.wait before touching
// producer outputs. Hides the ~4us/node launch ramp of nodes 2 and 3.
// ---------------------------------------------------------------------------

#define B_   8
#define C_   64
#define H_   28
#define W_   28
#define WP   30
#define NX   (B_ * C_ * H_ * W_)   // 401408
#define NW   (C_ * C_ * 9)         // 36864

#define AB_GRID 148
#define AB_THR  (AB_GRID * 256)

__device__ __forceinline__ void pdl_launch_dependents() {
    asm volatile("griddepcontrol.launch_dependents;" ::: "memory");
}
__device__ __forceinline__ void pdl_wait() {
    asm volatile("griddepcontrol.wait;" ::: "memory");
}

// device scratch (allocation-free). absmax/count reset by finishing block.
__device__ unsigned int g_absmax[2];
__device__ unsigned int g_count;
__device__ float        g_scales[3];          // s_x, s_w, s_x*s_w
__device__ signed char  g_qw[C_ * 9 * C_];    // [co][kh][kw][ci]

__device__ __forceinline__ int quant1(float v, float s) {
    float q = rintf(__fdiv_rn(v, s));
    q = fminf(fmaxf(q, -128.0f), 127.0f);
    return (int)q;
}
__device__ __forceinline__ float amax4(float4 v) {
    return fmaxf(fmaxf(fabsf(v.x), fabsf(v.y)), fmaxf(fabsf(v.z), fabsf(v.w)));
}

// ---------------------------------------------------------------------------
// Node 1: absmax(x), absmax(w) -> scales (last-block finalize + reset)
// ---------------------------------------------------------------------------
__global__ __launch_bounds__(256) void absmax_kernel(
    const float* __restrict__ x, const float* __restrict__ w)
{
    pdl_launch_dependents();          // let node 2 spin up + prefetch
    const int tid  = threadIdx.x;
    const int gtid = blockIdx.x * 256 + tid;
    __shared__ float s_red[16];

    float mx = 0.0f;
    {
        const float4* x4 = (const float4*)x;
        float m0 = 0.f, m1 = 0.f, m2 = 0.f;
        int i0 = gtid, i1 = gtid + AB_THR, i2 = gtid + 2 * AB_THR;
        if (i2 < NX / 4) {
            m0 = amax4(x4[i0]); m1 = amax4(x4[i1]); m2 = amax4(x4[i2]);
        } else if (i1 < NX / 4) {
            m0 = amax4(x4[i0]); m1 = amax4(x4[i1]);
        } else if (i0 < NX / 4) {
            m0 = amax4(x4[i0]);
        }
        mx = fmaxf(fmaxf(m0, m1), m2);
    }
    float mw = 0.0f;
    if (gtid < NW / 4) mw = amax4(((const float4*)w)[gtid]);

    #pragma unroll
    for (int o = 16; o; o >>= 1) {
        mx = fmaxf(mx, __shfl_xor_sync(0xffffffffu, mx, o));
        mw = fmaxf(mw, __shfl_xor_sync(0xffffffffu, mw, o));
    }
    if ((tid & 31) == 0) { s_red[tid >> 5] = mx; s_red[8 + (tid >> 5)] = mw; }
    __syncthreads();

    if (tid == 0) {
        float a = 0.0f, b = 0.0f;
        #pragma unroll
        for (int i = 0; i < 8; i++) {
            a = fmaxf(a, s_red[i]);
            b = fmaxf(b, s_red[8 + i]);
        }
        atomicMax(&g_absmax[0], __float_as_uint(a));   // vals >= 0: uint order
        atomicMax(&g_absmax[1], __float_as_uint(b));
        __threadfence();
        unsigned int done = atomicAdd(&g_count, 1u);
        if (done == AB_GRID - 1) {
            __threadfence();
            float amx = __uint_as_float(g_absmax[0]);
            float amw = __uint_as_float(g_absmax[1]);
            float Tf = __fadd_rn(2.85f,  __fmul_rn(0.05f, amx));
            float Tw = __fadd_rn(0.285f, __fmul_rn(0.05f, amw));
            float sx = __fdiv_rn(Tf, 127.0f);
            float sw = __fdiv_rn(Tw, 127.0f);
            g_scales[0] = sx;
            g_scales[1] = sw;
            g_scales[2] = __fmul_rn(sx, sw);
            g_absmax[0] = 0u;       // reset for next graph replay
            g_absmax[1] = 0u;
            g_count     = 0u;
        }
    }
}

// ---------------------------------------------------------------------------
// Node 2: quantize weights. Prefetch floats pre-wait; quantize post-wait.
// Grid 36 x 256 = 9216 threads = NW/4 exactly.
// ---------------------------------------------------------------------------
__global__ __launch_bounds__(256) void quantw_kernel(const float* __restrict__ wgt)
{
    pdl_launch_dependents();          // let node 3 spin up + prefetch
    int j = blockIdx.x * 256 + threadIdx.x;   // [0, 9216)
    int cig = j & 15;                 // group of 4 ci
    int r   = j >> 4;                 // co*9 + kh*3 + kw
    int co  = r / 9;
    int khw = r - co * 9;
    const float* src = wgt + co * 576 + cig * 36 + khw;
    float v0 = src[0], v1 = src[9], v2 = src[18], v3 = src[27];  // prefetch

    pdl_wait();                       // scales ready
    float s = g_scales[1];
    int q0 = quant1(v0, s);
    int q1 = quant1(v1, s);
    int q2 = quant1(v2, s);
    int q3 = quant1(v3, s);
    ((int*)g_qw)[j] = (q0 & 255) | ((q1 & 255) << 8) |
                      ((q2 & 255) << 16) | (q3 << 24);
}

// ---------------------------------------------------------------------------
// Node 3: conv. Grid (28, 8, 2): (oh, b, co-half), 224 threads.
// Pre-wait: prefetch this block's 3 float input rows (24 floats/thread) and
// bias into registers. Post-wait: quantize regs->smem, stage qw, dp4a conv.
// ---------------------------------------------------------------------------
#define WROW_W 148                    // words per co row (144 + 4 pad)
#define XROW_W (WP * 16)              // 480 words per padded row

__global__ __launch_bounds__(224) void conv_kernel(
    const float* __restrict__ x, const float* __restrict__ bias,
    float* __restrict__ out)
{
    __shared__ int s_qw[32 * WROW_W];   // 18944 B
    __shared__ int s_x[3 * XROW_W];     // 5760 B

    const int oh  = blockIdx.x;
    const int b   = blockIdx.y;
    const int coh = blockIdx.z;
    const int tid = threadIdx.x;

    // ---- pre-wait: prefetch x rows (6 x 4 floats) + bias ----
    // i = tid + k*224 covers 16cg x 3kh x 28w = 1344 positions exactly
    float pf[6][4];
    #pragma unroll
    for (int k = 0; k < 6; k++) {
        int i  = tid + k * 224;
        int w  = i % W_;
        int r2 = i / W_;              // cg*3 + kh
        int kh = r2 % 3;
        int cg = r2 / 3;
        int r  = oh - 1 + kh;
        if (r >= 0 && r < H_) {
            const float* src = x + (b * 64 + cg * 4) * 784 + r * W_ + w;
            pf[k][0] = src[0];
            pf[k][1] = src[784];
            pf[k][2] = src[1568];
            pf[k][3] = src[2352];
        } else {
            pf[k][0] = pf[k][1] = pf[k][2] = pf[k][3] = 0.0f;  // quant(0)=0
        }
    }
    const int co_l = tid & 31;
    const int co   = coh * 32 + co_l;
    const float bco = bias[co];

    // zero border columns (wp = 0, 29): 96 words
    if (tid < 96) {
        int kh = tid / 32;
        int t2 = tid & 31;
        int wp = (t2 < 16) ? 0 : 29;
        s_x[(kh * WP + wp) * 16 + (t2 & 15)] = 0;
    }

    pdl_wait();                       // scales + g_qw ready

    const float sx   = g_scales[0];
    const float prod = g_scales[2];

    // quantize prefetched rows into s_x[kh][w+1][cg]
    #pragma unroll
    for (int k = 0; k < 6; k++) {
        int i  = tid + k * 224;
        int w  = i % W_;
        int r2 = i / W_;
        int kh = r2 % 3;
        int cg = r2 / 3;
        int q0 = quant1(pf[k][0], sx);
        int q1 = quant1(pf[k][1], sx);
        int q2 = quant1(pf[k][2], sx);
        int q3 = quant1(pf[k][3], sx);
        s_x[(kh * WP + w + 1) * 16 + cg] =
            (q0 & 255) | ((q1 & 255) << 8) | ((q2 & 255) << 16) | (q3 << 24);
    }

    // stage this half's weights (produced by node 2 on other SMs)
    {
        const int4* gw = (const int4*)(g_qw + coh * 32 * 576);
        for (int i = tid; i < 32 * 36; i += 224) {
            int cl = i / 36;
            int jj = i - cl * 36;
            ((int4*)(s_qw + cl * WROW_W))[jj] = __ldcg(gw + i);
        }
    }
    __syncthreads();

    const int owg = tid >> 5;         // 0..6
    const int* wbase = s_qw + co_l * WROW_W;

    int acc[4];
    #pragma unroll
    for (int i = 0; i < 4; i++) acc[i] = 0;

    #pragma unroll
    for (int kh = 0; kh < 3; kh++) {
        const int* xrow = s_x + kh * XROW_W + owg * 4 * 16;
        const int* wrow = wbase + kh * 48;
        #pragma unroll
        for (int jj = 0; jj < 12; jj++) {
            int4 w4 = *(const int4*)(wrow + jj * 4);
            #pragma unroll
            for (int i = 0; i < 4; i++) {
                int4 x4 = *(const int4*)(xrow + i * 16 + jj * 4);
                int a = acc[i];
                a = __dp4a(x4.x, w4.x, a);
                a = __dp4a(x4.y, w4.y, a);
                a = __dp4a(x4.z, w4.z, a);
                a = __dp4a(x4.w, w4.w, a);
                acc[i] = a;
            }
        }
    }

    float* obase = out + ((b * C_ + co) * H_ + oh) * W_ + owg * 4;
    #pragma unroll
    for (int i = 0; i < 4; i++)
        obase[i] = __fadd_rn(__fmul_rn((float)acc[i], prod), bco);
}

// ---------------------------------------------------------------------------
extern "C" void kernel_launch(void* const* d_in, const int* in_sizes, int n_in,
                              void* d_out, int out_size)
{
    const float* x    = (const float*)d_in[0];   // (8,64,28,28)
    const float* wgt  = (const float*)d_in[1];   // (64,64,3,3)
    const float* bias = (const float*)d_in[2];   // (64,)
    // d_in[3] = lut: lut[a+128,b+128] == a*b -> folded into integer MAC
    float* out = (float*)d_out;

    // Node 1: plain launch
    absmax_kernel<<<AB_GRID, 256>>>(x, wgt);

    // Nodes 2 & 3: programmatic dependent launch (overlap ramp with producer)
    cudaLaunchAttribute attr[1];
    attr[0].id = cudaLaunchAttributeProgrammaticStreamSerialization;
    attr[0].val.programmaticStreamSerializationAllowed = 1;

    {
        cudaLaunchConfig_t cfg = {};
        cfg.gridDim  = dim3(36, 1, 1);
        cfg.blockDim = dim3(256, 1, 1);
        cfg.stream   = 0;
        cfg.attrs    = attr;
        cfg.numAttrs = 1;
        cudaLaunchKernelEx(&cfg, quantw_kernel, wgt);
    }
    {
        cudaLaunchConfig_t cfg = {};
        cfg.gridDim  = dim3(H_, B_, 2);
        cfg.blockDim = dim3(224, 1, 1);
        cfg.stream   = 0;
        cfg.attrs    = attr;
        cfg.numAttrs = 1;
        cudaLaunchKernelEx(&cfg, conv_kernel, x, bias, out);
    }
    (void)in_sizes; (void)n_in; (void)out_size;
}

// round 8
// speedup vs baseline: 1.4349x; 1.0118x over previous
#include <cuda_runtime.h>
#include <cuda_bf16.h>
#include <cstdint>

// ---------------------------------------------------------------------------
// Quantized "LUT" conv == plain int8 conv (lut[a+128][b+128] == a*b exactly):
//   T_f = 2.85 + 0.05*max|x| ; T_w = 0.285 + 0.05*max|w|
//   s_x = T_f/127 ; s_w = T_w/127
//   out = int8conv(clip(rint(x/s_x)), clip(rint(w/s_w))) * (s_x*s_w) + bias
// Integer accumulation is bit-identical to the f32 reference.
//
// R8: R7 (3 nodes + PDL) with absmax rebuilt for occupancy: grid 392x256 =
// exactly NX/4 threads, one unconditional float4 load each (no guard chain,
// no loop). 2.65x warps/SM -> memory phase ~1us instead of latency-starved.
// ---------------------------------------------------------------------------

#define B_   8
#define C_   64
#define H_   28
#define W_   28
#define WP   30
#define NX   (B_ * C_ * H_ * W_)   // 401408
#define NW   (C_ * C_ * 9)         // 36864

#define AB_GRID 392                // 392*256 == NX/4 exactly

__device__ __forceinline__ void pdl_launch_dependents() {
    asm volatile("griddepcontrol.launch_dependents;" ::: "memory");
}
__device__ __forceinline__ void pdl_wait() {
    asm volatile("griddepcontrol.wait;" ::: "memory");
}

// device scratch (allocation-free). absmax/count reset by finishing block.
__device__ unsigned int g_absmax[2];
__device__ unsigned int g_count;
__device__ float        g_scales[3];          // s_x, s_w, s_x*s_w
__device__ signed char  g_qw[C_ * 9 * C_];    // [co][kh][kw][ci]

__device__ __forceinline__ int quant1(float v, float s) {
    float q = rintf(__fdiv_rn(v, s));
    q = fminf(fmaxf(q, -128.0f), 127.0f);
    return (int)q;
}
__device__ __forceinline__ float amax4(float4 v) {
    return fmaxf(fmaxf(fabsf(v.x), fabsf(v.y)), fmaxf(fabsf(v.z), fabsf(v.w)));
}

// ---------------------------------------------------------------------------
// Node 1: absmax(x), absmax(w) -> scales (last-block finalize + reset)
// One unconditional float4 per thread; first NW/4 threads also cover w.
// ---------------------------------------------------------------------------
__global__ __launch_bounds__(256) void absmax_kernel(
    const float* __restrict__ x, const float* __restrict__ w)
{
    pdl_launch_dependents();          // let node 2 spin up + prefetch
    const int tid  = threadIdx.x;
    const int gtid = blockIdx.x * 256 + tid;
    __shared__ float s_red[16];

    float mx = amax4(((const float4*)x)[gtid]);       // gtid < NX/4 always
    float mw = 0.0f;
    if (gtid < NW / 4) mw = amax4(((const float4*)w)[gtid]);

    #pragma unroll
    for (int o = 16; o; o >>= 1) {
        mx = fmaxf(mx, __shfl_xor_sync(0xffffffffu, mx, o));
        mw = fmaxf(mw, __shfl_xor_sync(0xffffffffu, mw, o));
    }
    if ((tid & 31) == 0) { s_red[tid >> 5] = mx; s_red[8 + (tid >> 5)] = mw; }
    __syncthreads();

    if (tid == 0) {
        float a = 0.0f, b = 0.0f;
        #pragma unroll
        for (int i = 0; i < 8; i++) {
            a = fmaxf(a, s_red[i]);
            b = fmaxf(b, s_red[8 + i]);
        }
        atomicMax(&g_absmax[0], __float_as_uint(a));   // vals >= 0: uint order
        atomicMax(&g_absmax[1], __float_as_uint(b));
        __threadfence();
        unsigned int done = atomicAdd(&g_count, 1u);
        if (done == AB_GRID - 1) {
            __threadfence();
            float amx = __uint_as_float(g_absmax[0]);
            float amw = __uint_as_float(g_absmax[1]);
            float Tf = __fadd_rn(2.85f,  __fmul_rn(0.05f, amx));
            float Tw = __fadd_rn(0.285f, __fmul_rn(0.05f, amw));
            float sx = __fdiv_rn(Tf, 127.0f);
            float sw = __fdiv_rn(Tw, 127.0f);
            g_scales[0] = sx;
            g_scales[1] = sw;
            g_scales[2] = __fmul_rn(sx, sw);
            g_absmax[0] = 0u;       // reset for next graph replay
            g_absmax[1] = 0u;
            g_count     = 0u;
        }
    }
}

// ---------------------------------------------------------------------------
// Node 2: quantize weights. Prefetch floats pre-wait; quantize post-wait.
// Grid 36 x 256 = 9216 threads = NW/4 exactly.
// ---------------------------------------------------------------------------
__global__ __launch_bounds__(256) void quantw_kernel(const float* __restrict__ wgt)
{
    pdl_launch_dependents();          // let node 3 spin up + prefetch
    int j = blockIdx.x * 256 + threadIdx.x;   // [0, 9216)
    int cig = j & 15;                 // group of 4 ci
    int r   = j >> 4;                 // co*9 + kh*3 + kw
    int co  = r / 9;
    int khw = r - co * 9;
    const float* src = wgt + co * 576 + cig * 36 + khw;
    float v0 = src[0], v1 = src[9], v2 = src[18], v3 = src[27];  // prefetch

    pdl_wait();                       // scales ready
    float s = g_scales[1];
    int q0 = quant1(v0, s);
    int q1 = quant1(v1, s);
    int q2 = quant1(v2, s);
    int q3 = quant1(v3, s);
    ((int*)g_qw)[j] = (q0 & 255) | ((q1 & 255) << 8) |
                      ((q2 & 255) << 16) | (q3 << 24);
}

// ---------------------------------------------------------------------------
// Node 3: conv. Grid (28, 8, 2): (oh, b, co-half), 224 threads.
// Pre-wait: prefetch this block's 3 float input rows (24 floats/thread) and
// bias into registers. Post-wait: quantize regs->smem, stage qw, dp4a conv.
// ---------------------------------------------------------------------------
#define WROW_W 148                    // words per co row (144 + 4 pad)
#define XROW_W (WP * 16)              // 480 words per padded row

__global__ __launch_bounds__(224) void conv_kernel(
    const float* __restrict__ x, const float* __restrict__ bias,
    float* __restrict__ out)
{
    __shared__ int s_qw[32 * WROW_W];   // 18944 B
    __shared__ int s_x[3 * XROW_W];     // 5760 B

    const int oh  = blockIdx.x;
    const int b   = blockIdx.y;
    const int coh = blockIdx.z;
    const int tid = threadIdx.x;

    // ---- pre-wait: prefetch x rows (6 x 4 floats) + bias ----
    // i = tid + k*224 covers 16cg x 3kh x 28w = 1344 positions exactly
    float pf[6][4];
    #pragma unroll
    for (int k = 0; k < 6; k++) {
        int i  = tid + k * 224;
        int w  = i % W_;
        int r2 = i / W_;              // cg*3 + kh
        int kh = r2 % 3;
        int cg = r2 / 3;
        int r  = oh - 1 + kh;
        if (r >= 0 && r < H_) {
            const float* src = x + (b * 64 + cg * 4) * 784 + r * W_ + w;
            pf[k][0] = src[0];
            pf[k][1] = src[784];
            pf[k][2] = src[1568];
            pf[k][3] = src[2352];
        } else {
            pf[k][0] = pf[k][1] = pf[k][2] = pf[k][3] = 0.0f;  // quant(0)=0
        }
    }
    const int co_l = tid & 31;
    const int co   = coh * 32 + co_l;
    const float bco = bias[co];

    // zero border columns (wp = 0, 29): 96 words
    if (tid < 96) {
        int kh = tid / 32;
        int t2 = tid & 31;
        int wp = (t2 < 16) ? 0 : 29;
        s_x[(kh * WP + wp) * 16 + (t2 & 15)] = 0;
    }

    pdl_wait();                       // scales + g_qw ready

    const float sx   = g_scales[0];
    const float prod = g_scales[2];

    // quantize prefetched rows into s_x[kh][w+1][cg]
    #pragma unroll
    for (int k = 0; k < 6; k++) {
        int i  = tid + k * 224;
        int w  = i % W_;
        int r2 = i / W_;
        int kh = r2 % 3;
        int cg = r2 / 3;
        int q0 = quant1(pf[k][0], sx);
        int q1 = quant1(pf[k][1], sx);
        int q2 = quant1(pf[k][2], sx);
        int q3 = quant1(pf[k][3], sx);
        s_x[(kh * WP + w + 1) * 16 + cg] =
            (q0 & 255) | ((q1 & 255) << 8) | ((q2 & 255) << 16) | (q3 << 24);
    }

    // stage this half's weights (produced by node 2 on other SMs)
    {
        const int4* gw = (const int4*)(g_qw + coh * 32 * 576);
        for (int i = tid; i < 32 * 36; i += 224) {
            int cl = i / 36;
            int jj = i - cl * 36;
            ((int4*)(s_qw + cl * WROW_W))[jj] = __ldcg(gw + i);
        }
    }
    __syncthreads();

    const int owg = tid >> 5;         // 0..6
    const int* wbase = s_qw + co_l * WROW_W;

    int acc[4];
    #pragma unroll
    for (int i = 0; i < 4; i++) acc[i] = 0;

    #pragma unroll
    for (int kh = 0; kh < 3; kh++) {
        const int* xrow = s_x + kh * XROW_W + owg * 4 * 16;
        const int* wrow = wbase + kh * 48;
        #pragma unroll
        for (int jj = 0; jj < 12; jj++) {
            int4 w4 = *(const int4*)(wrow + jj * 4);
            #pragma unroll
            for (int i = 0; i < 4; i++) {
                int4 x4 = *(const int4*)(xrow + i * 16 + jj * 4);
                int a = acc[i];
                a = __dp4a(x4.x, w4.x, a);
                a = __dp4a(x4.y, w4.y, a);
                a = __dp4a(x4.z, w4.z, a);
                a = __dp4a(x4.w, w4.w, a);
                acc[i] = a;
            }
        }
    }

    float* obase = out + ((b * C_ + co) * H_ + oh) * W_ + owg * 4;
    #pragma unroll
    for (int i = 0; i < 4; i++)
        obase[i] = __fadd_rn(__fmul_rn((float)acc[i], prod), bco);
}

// ---------------------------------------------------------------------------
extern "C" void kernel_launch(void* const* d_in, const int* in_sizes, int n_in,
                              void* d_out, int out_size)
{
    const float* x    = (const float*)d_in[0];   // (8,64,28,28)
    const float* wgt  = (const float*)d_in[1];   // (64,64,3,3)
    const float* bias = (const float*)d_in[2];   // (64,)
    // d_in[3] = lut: lut[a+128,b+128] == a*b -> folded into integer MAC
    float* out = (float*)d_out;

    // Node 1: plain launch
    absmax_kernel<<<AB_GRID, 256>>>(x, wgt);

    // Nodes 2 & 3: programmatic dependent launch (overlap ramp with producer)
    cudaLaunchAttribute attr[1];
    attr[0].id = cudaLaunchAttributeProgrammaticStreamSerialization;
    attr[0].val.programmaticStreamSerializationAllowed = 1;

    {
        cudaLaunchConfig_t cfg = {};
        cfg.gridDim  = dim3(36, 1, 1);
        cfg.blockDim = dim3(256, 1, 1);
        cfg.stream   = 0;
        cfg.attrs    = attr;
        cfg.numAttrs = 1;
        cudaLaunchKernelEx(&cfg, quantw_kernel, wgt);
    }
    {
        cudaLaunchConfig_t cfg = {};
        cfg.gridDim  = dim3(H_, B_, 2);
        cfg.blockDim = dim3(224, 1, 1);
        cfg.stream   = 0;
        cfg.attrs    = attr;
        cfg.numAttrs = 1;
        cudaLaunchKernelEx(&cfg, conv_kernel, x, bias, out);
    }
    (void)in_sizes; (void)n_in; (void)out_size;
}